// round 13
// baseline (speedup 1.0000x reference)
#include <cuda_runtime.h>

#define Hh 1024
#define Ww 1024
#define Bb 16
#define DIL 2
#define NTHREADS 256
#define SPB 37                              // strips (blocks) per image
#define NBLOCKS (Bb * SPB)                  // 592 = 4 * 148 SMs: one exact wave
#define NELEM ((long long)Bb * Hh * Ww)

#define NEG100_LG2 (-144.269504088896f)     // -100 / ln(2)
#define LN2F (0.6931471805599453f)

__device__ double       g_sum   = 0.0;
__device__ unsigned int g_count = 0u;

// Per-row separable state: horizontal 3-point (dilated) min/max INCLUDING the
// center (valid: uw = max(p-mn, mx-p) >= 0), plus the 4 center pixels.
struct RowS {
    float mn[4], mx[4], cen[4];
};

__device__ __forceinline__ void load_row(RowS& s, const float* __restrict__ img,
                                         int gy, int x4, bool leftEdge, bool rightEdge) {
    float4 L = make_float4(0.f, 0.f, 0.f, 0.f);
    float4 C = L, R = L;
    if (gy >= 0 && gy < Hh) {                       // uniform across the warp
        const float* r = img + (size_t)gy * Ww;
        if (!leftEdge)  L = *reinterpret_cast<const float4*>(r + x4 - 4);
        C = *reinterpret_cast<const float4*>(r + x4);
        if (!rightEdge) R = *reinterpret_cast<const float4*>(r + x4 + 4);
    }
    s.mn[0] = fminf(fminf(L.z, C.x), C.z);
    s.mn[1] = fminf(fminf(L.w, C.y), C.w);
    s.mn[2] = fminf(fminf(C.x, C.z), R.x);
    s.mn[3] = fminf(fminf(C.y, C.w), R.y);
    s.mx[0] = fmaxf(fmaxf(L.z, C.x), C.z);
    s.mx[1] = fmaxf(fmaxf(L.w, C.y), C.w);
    s.mx[2] = fmaxf(fmaxf(C.x, C.z), R.x);
    s.mx[3] = fmaxf(fmaxf(C.y, C.w), R.y);
    s.cen[0] = C.x; s.cen[1] = C.y; s.cen[2] = C.z; s.cen[3] = C.w;
}

__device__ __forceinline__ void row_loss(const RowS& up, const RowS& mid, const RowS& dn,
                                         float4 t4,
                                         float& uw_acc, float& a_tLp,
                                         float& a_tL1, float& a_L1) {
    const float tval[4] = { t4.x, t4.y, t4.z, t4.w };
#pragma unroll
    for (int k = 0; k < 4; ++k) {
        const float p = mid.cen[k];
        const float t = tval[k];

        const float mn = fminf(fminf(up.mn[k], dn.mn[k]), mid.mn[k]);
        const float mx = fmaxf(fmaxf(up.mx[k], dn.mx[k]), mid.mx[k]);
        const float uw = fmaxf(p - mn, mx - p);     // == max_nb |p - nb|

        if (p >= 0.5f)                              // thred: predicated FFMA
            uw_acc = fmaf(uw, p, uw_acc);

        // Lp needs the -100 clamp (p can be 0). L1 does not (1-p >= 2^-24).
        const float Lp = fmaxf(__log2f(p), NEG100_LG2);
        const float L1 = __log2f(1.0f - p);
        a_tLp = fmaf(t, Lp, a_tLp);
        a_tL1 = fmaf(t, L1, a_tL1);
        a_L1 += L1;
    }
}

__global__ __launch_bounds__(NTHREADS, 4)
void consistency_main(const float* __restrict__ yt, const float* __restrict__ yp,
                      float* __restrict__ out) {
    __shared__ float warp_sums[NTHREADS / 32];

    const int blk = blockIdx.x;                     // 0..591
    const int b   = blk / SPB;                      // image
    const int s   = blk - b * SPB;                  // strip slot 0..36
    const int r0  = (s * Hh) / SPB;                 // strip rows [r0, r1)
    const int r1  = ((s + 1) * Hh) / SPB;           // 27 or 28 rows
    const int tid = threadIdx.x;
    const int x4  = tid * 4;
    const bool leftEdge  = (tid == 0);
    const bool rightEdge = (tid == NTHREADS - 1);

    const float* img  = yp + (size_t)b * Hh * Ww;
    const float* timg = yt + (size_t)b * Hh * Ww;

    float uw_acc = 0.f, a_tLp = 0.f, a_tL1 = 0.f, a_L1 = 0.f;

    // Two parity chains over rows [r0, r1); vertical neighbors are +-2.
    // Double-step: rows j, j+2 per iteration with 8 front-batched LDG.128
    // (6 window rows + 2 y_true rows), then one 2-RowS rotation.
#pragma unroll 1
    for (int c = 0; c < 2; ++c) {
        int j = r0 + c;
        RowS ra, rb, rc, rd;
        load_row(ra, img, j - 2, x4, leftEdge, rightEdge);
        load_row(rb, img, j,     x4, leftEdge, rightEdge);

#pragma unroll 1
        for (; j + 2 < r1; j += 4) {
            load_row(rc, img, j + 2, x4, leftEdge, rightEdge);
            load_row(rd, img, j + 4, x4, leftEdge, rightEdge);
            const float4 tA = *reinterpret_cast<const float4*>(
                timg + (size_t)j * Ww + x4);
            const float4 tB = *reinterpret_cast<const float4*>(
                timg + (size_t)(j + 2) * Ww + x4);

            row_loss(ra, rb, rc, tA, uw_acc, a_tLp, a_tL1, a_L1);   // row j
            row_loss(rb, rc, rd, tB, uw_acc, a_tLp, a_tL1, a_L1);   // row j+2

            ra = rc; rb = rd;
        }
        if (j < r1) {                                // odd chain tail
            load_row(rc, img, j + 2, x4, leftEdge, rightEdge);
            const float4 tA = *reinterpret_cast<const float4*>(
                timg + (size_t)j * Ww + x4);
            row_loss(ra, rb, rc, tA, uw_acc, a_tLp, a_tL1, a_L1);
        }
    }

    // bce_sum(lg2) = -(Σ t·Lp + Σ L1 - Σ t·L1); fold ln2 once.
    float lsum = fmaf(LN2F, a_tL1 - a_tLp - a_L1, uw_acc);

    // Block reduction
#pragma unroll
    for (int off = 16; off > 0; off >>= 1)
        lsum += __shfl_xor_sync(0xFFFFFFFFu, lsum, off);
    if ((tid & 31) == 0) warp_sums[tid >> 5] = lsum;
    __syncthreads();
    if (tid == 0) {
        float v = 0.f;
#pragma unroll
        for (int w = 0; w < NTHREADS / 32; ++w) v += warp_sums[w];

        // Fused final reduction: last-arriving block writes the mean.
        atomicAdd(&g_sum, (double)v);
        __threadfence();
        const unsigned int old = atomicAdd(&g_count, 1u);
        if (old == NBLOCKS - 1) {
            const double total = atomicAdd(&g_sum, 0.0);   // coherent read
            out[0] = (float)(total / (double)NELEM);
            g_sum   = 0.0;                                  // reset for next replay
            __threadfence();
            g_count = 0u;
        }
    }
}

extern "C" void kernel_launch(void* const* d_in, const int* in_sizes, int n_in,
                              void* d_out, int out_size) {
    const float* y_true = (const float*)d_in[0];
    const float* y_pred = (const float*)d_in[1];
    float* out = (float*)d_out;
    consistency_main<<<NBLOCKS, NTHREADS>>>(y_true, y_pred, out);
}

// round 14
// speedup vs baseline: 1.0482x; 1.0482x over previous
#include <cuda_runtime.h>

#define Hh 1024
#define Ww 1024
#define Bb 16
#define NTHREADS 256
#define SPB 37                              // strips per image
#define NBLOCKS (Bb * SPB)                  // 592 = 4 * 148 SMs: one exact wave
#define NELEM ((long long)Bb * Hh * Ww)

#define NEG100_LG2 (-144.269504088896f)     // -100 / ln(2)
#define LN2F (0.6931471805599453f)

__device__ double       g_sum   = 0.0;
__device__ unsigned int g_count = 0u;

// Per-row separable state: horizontal 3-point dilated min/max INCLUDING the
// center (valid since uw = max(p-mn, mx-p) >= 0), plus the 4 center pixels.
struct RowS {
    float mn[4], mx[4], cen[4];
};

// rowbase = img + gy*Ww maintained by pointer increments at the call sites.
__device__ __forceinline__ void load_row(RowS& s, const float* __restrict__ rowbase,
                                         int gy, int x4, bool le, bool re) {
    float4 L = make_float4(0.f, 0.f, 0.f, 0.f);
    float4 C = L, R = L;
    if (gy >= 0 && gy < Hh) {                       // uniform across the warp
        if (!le) L = *reinterpret_cast<const float4*>(rowbase + x4 - 4);
        C = *reinterpret_cast<const float4*>(rowbase + x4);
        if (!re) R = *reinterpret_cast<const float4*>(rowbase + x4 + 4);
    }
    s.mn[0] = fminf(fminf(L.z, C.x), C.z);
    s.mn[1] = fminf(fminf(L.w, C.y), C.w);
    s.mn[2] = fminf(fminf(C.x, C.z), R.x);
    s.mn[3] = fminf(fminf(C.y, C.w), R.y);
    s.mx[0] = fmaxf(fmaxf(L.z, C.x), C.z);
    s.mx[1] = fmaxf(fmaxf(L.w, C.y), C.w);
    s.mx[2] = fmaxf(fmaxf(C.x, C.z), R.x);
    s.mx[3] = fmaxf(fmaxf(C.y, C.w), R.y);
    s.cen[0] = C.x; s.cen[1] = C.y; s.cen[2] = C.z; s.cen[3] = C.w;
}

__device__ __forceinline__ void row_loss(const RowS& up, const RowS& mid, const RowS& dn,
                                         float4 t4,
                                         float& uw_acc, float& a_tLp,
                                         float& a_tL1, float& a_L1) {
    const float tval[4] = { t4.x, t4.y, t4.z, t4.w };
#pragma unroll
    for (int k = 0; k < 4; ++k) {
        const float p = mid.cen[k];
        const float t = tval[k];

        const float mn = fminf(fminf(up.mn[k], dn.mn[k]), mid.mn[k]);
        const float mx = fmaxf(fmaxf(up.mx[k], dn.mx[k]), mid.mx[k]);
        const float uw = fmaxf(p - mn, mx - p);     // == max_nb |p - nb|

        if (p >= 0.5f)                              // thred: predicated FFMA
            uw_acc = fmaf(uw, p, uw_acc);

        // Lp needs the -100 clamp (p can be 0). L1 does not (1-p >= 2^-24).
        const float Lp = fmaxf(__log2f(p), NEG100_LG2);
        const float L1 = __log2f(1.0f - p);
        a_tLp = fmaf(t, Lp, a_tLp);
        a_tL1 = fmaf(t, L1, a_tL1);
        a_L1 += L1;
    }
}

__global__ __launch_bounds__(NTHREADS, 4)
void consistency_main(const float* __restrict__ yt, const float* __restrict__ yp,
                      float* __restrict__ out) {
    __shared__ float warp_sums[NTHREADS / 32];

    const int blk = blockIdx.x;                     // 0..591
    const int b   = blk / SPB;                      // image
    const int s   = blk - b * SPB;                  // strip slot 0..36
    const int r0  = (s * Hh) / SPB;                 // strip rows [r0, r1)
    const int r1  = ((s + 1) * Hh) / SPB;           // 27 or 28 rows
    const int tid = threadIdx.x;
    const int x4  = tid * 4;
    const bool le = (tid == 0);
    const bool re = (tid == NTHREADS - 1);

    const float* img  = yp + (size_t)b * Hh * Ww;
    const float* timg = yt + (size_t)b * Hh * Ww;

    float uw_acc = 0.f, a_tLp = 0.f, a_tL1 = 0.f, a_L1 = 0.f;

    // Two parity chains over [r0, r1); vertical neighbors are +-2.
    // Software-pipelined unroll-3: (rA,rB,rC) rotate by NAME each body, so the
    // steady-state loop carries no rotation MOVs. Pointers advance by 2 rows.
#pragma unroll 1
    for (int c = 0; c < 2; ++c) {
        int j = r0 + c;                             // next row to compute
        RowS rA, rB, rC;
        const float* pl = img + (ptrdiff_t)(j - 2) * Ww;   // next row to LOAD
        int gyl = j - 2;
        load_row(rA, pl, gyl, x4, le, re); pl += 2 * Ww; gyl += 2;
        load_row(rB, pl, gyl, x4, le, re); pl += 2 * Ww; gyl += 2;
        const float* tp = timg + (ptrdiff_t)j * Ww + x4;   // y_true of row j

#pragma unroll 1
        for (; j + 4 < r1; j += 6) {
            // body 1: compute row j with (rA, rB, rC)
            load_row(rC, pl, gyl, x4, le, re); pl += 2 * Ww; gyl += 2;
            float4 t0 = *reinterpret_cast<const float4*>(tp); tp += 2 * Ww;
            row_loss(rA, rB, rC, t0, uw_acc, a_tLp, a_tL1, a_L1);
            // body 2: compute row j+2 with (rB, rC, rA)
            load_row(rA, pl, gyl, x4, le, re); pl += 2 * Ww; gyl += 2;
            float4 t1 = *reinterpret_cast<const float4*>(tp); tp += 2 * Ww;
            row_loss(rB, rC, rA, t1, uw_acc, a_tLp, a_tL1, a_L1);
            // body 3: compute row j+4 with (rC, rA, rB)
            load_row(rB, pl, gyl, x4, le, re); pl += 2 * Ww; gyl += 2;
            float4 t2 = *reinterpret_cast<const float4*>(tp); tp += 2 * Ww;
            row_loss(rC, rA, rB, t2, uw_acc, a_tLp, a_tL1, a_L1);
            // names now cycle back: rA = row j+4, rB = row j+6 ✓
        }
        // remainder: at most 2 rows left in this chain
        if (j < r1) {
            load_row(rC, pl, gyl, x4, le, re); pl += 2 * Ww; gyl += 2;
            float4 t0 = *reinterpret_cast<const float4*>(tp); tp += 2 * Ww;
            row_loss(rA, rB, rC, t0, uw_acc, a_tLp, a_tL1, a_L1);
            rA = rB; rB = rC;                       // one real rotation
            j += 2;
        }
        if (j < r1) {
            load_row(rC, pl, gyl, x4, le, re);
            float4 t0 = *reinterpret_cast<const float4*>(tp);
            row_loss(rA, rB, rC, t0, uw_acc, a_tLp, a_tL1, a_L1);
        }
    }

    // bce_sum(lg2) = -(Σ t·Lp + Σ L1 - Σ t·L1); fold ln2 once.
    float lsum = fmaf(LN2F, a_tL1 - a_tLp - a_L1, uw_acc);

    // Block reduction
#pragma unroll
    for (int off = 16; off > 0; off >>= 1)
        lsum += __shfl_xor_sync(0xFFFFFFFFu, lsum, off);
    if ((tid & 31) == 0) warp_sums[tid >> 5] = lsum;
    __syncthreads();
    if (tid == 0) {
        float v = 0.f;
#pragma unroll
        for (int w = 0; w < NTHREADS / 32; ++w) v += warp_sums[w];

        // Fused final reduction: last-arriving block writes the mean.
        atomicAdd(&g_sum, (double)v);
        __threadfence();
        const unsigned int old = atomicAdd(&g_count, 1u);
        if (old == NBLOCKS - 1) {
            const double total = atomicAdd(&g_sum, 0.0);   // coherent read
            out[0] = (float)(total / (double)NELEM);
            g_sum   = 0.0;                                  // reset for next replay
            __threadfence();
            g_count = 0u;
        }
    }
}

extern "C" void kernel_launch(void* const* d_in, const int* in_sizes, int n_in,
                              void* d_out, int out_size) {
    const float* y_true = (const float*)d_in[0];
    const float* y_pred = (const float*)d_in[1];
    float* out = (float*)d_out;
    consistency_main<<<NBLOCKS, NTHREADS>>>(y_true, y_pred, out);
}